// round 9
// baseline (speedup 1.0000x reference)
#include <cuda_runtime.h>
#include <cuda_bf16.h>
#include <cstdint>

// Grouped conv2d via implicit GEMM on mma.sync (HMMA), split-bf16 3-pass.
// x[16,256,128,128] * W[512,16,3,3] (groups=16) + b -> out[16,512,128,128]
// R9: interleaved hi/lo x plane (64B/px, 8B {hi,lo} per ci-pair), 2-bit swizzle
//     (addr bits 8,9 -> 4,5). A = 2x LDS.128/tap-seg. Staging = STS.64, ~2-way.

#define THREADS 256

// ---- smem layout (bytes) ----
#define SWF_OFF   0
#define SWF_BYTES (18 * 1024)               // B frags, 16B-block XOR swizzle (bit7->4)
// x plane: [row 0..5][col 0..129] x 64B: 8 pair-slots of 8B {hi_u32, lo_u32}
#define XCOL_STRIDE 64
#define XROW_STRIDE (130 * XCOL_STRIDE)     // 8320
#define SX_OFF    SWF_BYTES                 // 18432 (bits 4..10 clear)
#define SX_BYTES  (6 * XROW_STRIDE)         // 49920
#define SBIAS_OFF (SX_OFF + SX_BYTES)       // 68352
#define SMEM_TOTAL (SBIAS_OFF + 128)        // 68480  (x3 = 205440 <= 228KB)

__device__ __forceinline__ void mma16816(float& c0, float& c1, float& c2, float& c3,
                                         uint32_t a0, uint32_t a1, uint32_t a2, uint32_t a3,
                                         uint32_t b0, uint32_t b1) {
    asm volatile("mma.sync.aligned.m16n8k16.row.col.f32.bf16.bf16.f32 "
                 "{%0,%1,%2,%3}, {%4,%5,%6,%7}, {%8,%9}, {%0,%1,%2,%3};"
                 : "+f"(c0), "+f"(c1), "+f"(c2), "+f"(c3)
                 : "r"(a0), "r"(a1), "r"(a2), "r"(a3), "r"(b0), "r"(b1));
}

__device__ __forceinline__ uint32_t bf16_hi_lo_pack(float v0, float v1, int want_lo) {
    __nv_bfloat16 h0 = __float2bfloat16(v0);
    __nv_bfloat16 h1 = __float2bfloat16(v1);
    __nv_bfloat16 e0, e1;
    if (want_lo) {
        e0 = __float2bfloat16(v0 - __bfloat162float(h0));
        e1 = __float2bfloat16(v1 - __bfloat162float(h1));
    } else {
        e0 = h0; e1 = h1;
    }
    return (uint32_t)__bfloat16_as_ushort(e0) | ((uint32_t)__bfloat16_as_ushort(e1) << 16);
}

// x-plane swizzle: fold addr bits 8,9 into bits 4,5 (preserves 16B alignment)
__device__ __forceinline__ uint32_t xswz(uint32_t a) {
    return a ^ ((a >> 4) & 0x30u);
}
// B-frag swizzle (16B blocks): fold bit7 into bit4
__device__ __forceinline__ uint32_t bswz(uint32_t a) {
    return a ^ (((a >> 7) & 1u) << 4);
}

__global__ __launch_bounds__(THREADS, 3)
void grouped_conv_hmma(const float* __restrict__ x,
                       const float* __restrict__ w,
                       const float* __restrict__ bias,
                       float* __restrict__ out)
{
    extern __shared__ char smem[];
    uint32_t* swf = (uint32_t*)(smem + SWF_OFF);
    char* sx = smem + SX_OFF;
    float* sbias = (float*)(smem + SBIAS_OFF);

    const int tid = threadIdx.x;
    const int wid = tid >> 5;
    const int lane = tid & 31;

    const int hb = blockIdx.x;          // 0..31  (4-row blocks)
    const int ng = blockIdx.y;          // 0..255
    const int n  = ng >> 4;
    const int g  = ng & 15;
    const int h0 = hb * 4;

    // ---- stage x: rows h0-1..h0+4 (r 0..5), cols c=1..128 via float4 chunks ----
    // pair j (ci 2j,2j+1) stored at pair-slot pj = (j&3)*2 + (j>>2), 8B {hi, lo}
    const float* xg = x + (size_t)(n * 256 + g * 16) * 16384;
    #pragma unroll
    for (int it0 = 0; it0 < 6; ++it0) {
        int it = tid + it0 * THREADS;      // 0..1535
        int j  = it & 7;
        int m  = (it >> 3) & 3;
        int ch = (it >> 5) & 7;
        int r  = it >> 8;                  // 0..5
        int cc = ch * 4 + m;               // 0..31
        int gw0 = cc * 4;                  // aligned float4 col
        int gh  = h0 - 1 + r;
        float4 v0 = make_float4(0.f, 0.f, 0.f, 0.f);
        float4 v1 = v0;
        if ((unsigned)gh < 128u) {
            const float* p = xg + (size_t)(2 * j) * 16384 + gh * 128 + gw0;
            v0 = *(const float4*)p;
            v1 = *(const float4*)(p + 16384);
        }
        int pj = (j & 3) * 2 + (j >> 2);
        uint32_t base = (uint32_t)(r * XROW_STRIDE + (1 + cc * 4) * XCOL_STRIDE + pj * 8);
        float a0[4] = {v0.x, v0.y, v0.z, v0.w};
        float a1[4] = {v1.x, v1.y, v1.z, v1.w};
        #pragma unroll
        for (int k = 0; k < 4; ++k) {
            uint2 u;
            u.x = bf16_hi_lo_pack(a0[k], a1[k], 0);
            u.y = bf16_hi_lo_pack(a0[k], a1[k], 1);
            *(uint2*)(sx + xswz(base + (uint32_t)(k * XCOL_STRIDE))) = u;
        }
    }
    // edge cols c=0 and c=129 -> zeros
    if (tid < 96) {
        int e = tid & 1;                   // 0 -> c=0, 1 -> c=129
        int j = (tid >> 1) & 7;
        int r = tid >> 4;                  // 0..5
        int pj = (j & 3) * 2 + (j >> 2);
        uint32_t a = (uint32_t)(r * XROW_STRIDE + (e ? 129 : 0) * XCOL_STRIDE + pj * 8);
        uint2 z; z.x = 0u; z.y = 0u;
        *(uint2*)(sx + xswz(a)) = z;
    }

    // ---- stage W as B fragments, XOR-swizzled 32B/lane ----
    const float* wgp = w + (size_t)(g * 32) * 144;
    for (int idx = tid; idx < 18 * 32 * 8; idx += THREADS) {
        int slot  = idx & 7;
        int lane2 = (idx >> 3) & 31;
        int combo = idx >> 8;           // 0..17 = tap*2 + hl
        int tap = combo >> 1, hl = combo & 1;
        int g4 = lane2 >> 2, t4 = lane2 & 3;
        int nt = slot >> 1, rr = slot & 1;
        int co  = nt * 8 + g4;
        int ci0 = 2 * t4 + 8 * rr;
        float v0 = wgp[co * 144 + ci0 * 9 + tap];
        float v1 = wgp[co * 144 + (ci0 + 1) * 9 + tap];
        uint32_t logical = (uint32_t)(combo * 1024 + lane2 * 32 + slot * 4);
        *(uint32_t*)((char*)swf + bswz(logical)) = bf16_hi_lo_pack(v0, v1, hl);
    }
    if (tid < 32) sbias[tid] = bias[g * 32 + tid];
    __syncthreads();

    // ---- main: warp = (row, w-half); 2 halves of 2 segs each ----
    const int wrow  = wid >> 1;          // 0..3
    const int whalf = (wid & 1) * 64;
    const int g4 = lane >> 2, t4 = lane & 3;
    const int h = h0 + wrow;
    float* og = out + (size_t)(n * 512 + g * 32) * 16384 + (size_t)h * 128;

    const uint32_t pxoff = (uint32_t)(g4 * XCOL_STRIDE + t4 * 16);
    const uint32_t bswF = bswz((uint32_t)(lane * 32));

    #pragma unroll
    for (int half = 0; half < 2; ++half) {
        float acc[2][4][4];              // [seg2][nt][4]
        #pragma unroll
        for (int s = 0; s < 2; ++s)
            #pragma unroll
            for (int nt = 0; nt < 4; ++nt)
                #pragma unroll
                for (int i = 0; i < 4; ++i) acc[s][nt][i] = 0.0f;

        #pragma unroll 3
        for (int tap = 0; tap < 9; ++tap) {
            const int dh = tap / 3, dw = tap % 3;
            const uint32_t bo = (uint32_t)(tap * 2048) + bswF;
            uint4 bh0 = *(const uint4*)((const char*)swf + bo);
            uint4 bh1 = *(const uint4*)((const char*)swf + (bo ^ 16));
            uint4 bl0 = *(const uint4*)((const char*)swf + bo + 1024);
            uint4 bl1 = *(const uint4*)((const char*)swf + (bo ^ 16) + 1024);

            const uint32_t rowB = (uint32_t)((wrow + dh) * XROW_STRIDE + dw * XCOL_STRIDE) + pxoff;

            #pragma unroll
            for (int s = 0; s < 2; ++s) {
                const int w0 = whalf + (half * 2 + s) * 16;
                const uint32_t off  = rowB + (uint32_t)(w0 * XCOL_STRIDE);
                const uint32_t off2 = off + 512;          // px + 8
                uint4 v = *(const uint4*)(sx + xswz(off));
                uint4 u = *(const uint4*)(sx + xswz(off2));
                // v = {a0hi, a0lo, a2hi, a2lo}, u = {a1hi, a1lo, a3hi, a3lo}

                float* a0 = acc[s][0];
                float* a1 = acc[s][1];
                float* a2 = acc[s][2];
                float* a3 = acc[s][3];

                mma16816(a0[0], a0[1], a0[2], a0[3], v.x, u.x, v.z, u.z, bh0.x, bh0.y);
                mma16816(a1[0], a1[1], a1[2], a1[3], v.x, u.x, v.z, u.z, bh0.z, bh0.w);
                mma16816(a2[0], a2[1], a2[2], a2[3], v.x, u.x, v.z, u.z, bh1.x, bh1.y);
                mma16816(a3[0], a3[1], a3[2], a3[3], v.x, u.x, v.z, u.z, bh1.z, bh1.w);

                mma16816(a0[0], a0[1], a0[2], a0[3], v.x, u.x, v.z, u.z, bl0.x, bl0.y);
                mma16816(a1[0], a1[1], a1[2], a1[3], v.x, u.x, v.z, u.z, bl0.z, bl0.w);
                mma16816(a2[0], a2[1], a2[2], a2[3], v.x, u.x, v.z, u.z, bl1.x, bl1.y);
                mma16816(a3[0], a3[1], a3[2], a3[3], v.x, u.x, v.z, u.z, bl1.z, bl1.w);

                mma16816(a0[0], a0[1], a0[2], a0[3], v.y, u.y, v.w, u.w, bh0.x, bh0.y);
                mma16816(a1[0], a1[1], a1[2], a1[3], v.y, u.y, v.w, u.w, bh0.z, bh0.w);
                mma16816(a2[0], a2[1], a2[2], a2[3], v.y, u.y, v.w, u.w, bh1.x, bh1.y);
                mma16816(a3[0], a3[1], a3[2], a3[3], v.y, u.y, v.w, u.w, bh1.z, bh1.w);
            }
        }

        // ---- epilogue for this half ----
        #pragma unroll
        for (int s = 0; s < 2; ++s) {
            const int w0 = whalf + (half * 2 + s) * 16;
            #pragma unroll
            for (int nt = 0; nt < 4; ++nt) {
                const float blo = sbias[nt * 8 + 2 * t4];
                const float bhi = sbias[nt * 8 + 2 * t4 + 1];
                const size_t co0 = (size_t)(nt * 8 + 2 * t4) * 16384;
                og[co0 + w0 + g4]             = acc[s][nt][0] + blo;
                og[co0 + 16384 + w0 + g4]     = acc[s][nt][1] + bhi;
                og[co0 + w0 + g4 + 8]         = acc[s][nt][2] + blo;
                og[co0 + 16384 + w0 + g4 + 8] = acc[s][nt][3] + bhi;
            }
        }
    }
}

extern "C" void kernel_launch(void* const* d_in, const int* in_sizes, int n_in,
                              void* d_out, int out_size)
{
    const float* x = (const float*)d_in[0];
    const float* w = (const float*)d_in[1];
    const float* b = (const float*)d_in[2];
    float* out = (float*)d_out;

    cudaFuncSetAttribute(grouped_conv_hmma,
                         cudaFuncAttributeMaxDynamicSharedMemorySize, SMEM_TOTAL);

    dim3 grid(32, 256);   // 4-row h blocks, n*16+g
    grouped_conv_hmma<<<grid, THREADS, SMEM_TOTAL>>>(x, w, b, out);
}

// round 10
// speedup vs baseline: 1.9105x; 1.9105x over previous
#include <cuda_runtime.h>
#include <cuda_fp16.h>
#include <cstdint>

// Grouped conv2d via implicit GEMM on mma.sync (HMMA), SINGLE-PASS fp16.
// x[16,256,128,128] * W[512,16,3,3] (groups=16) + b -> out[16,512,128,128]
// R10: fp16 inputs, fp32 accum (aggregate rel err ~1.4e-4 << 1e-3 norm metric).
// 4 CTAs/SM (34KB smem, 64 regs). Warp = (row, w-half), 2 halves x 2 segs.

#define THREADS 256

// ---- smem layout (bytes) ----
// B frags: 9 taps x 1024B (32 lanes x 32B), 16B-block XOR swizzle (bit7->4)
#define SWF_OFF   0
#define SWF_BYTES (9 * 1024)                // 9216
// x plane: [row 0..5][col 0..129] x 32B (16 ci fp16, permuted pairs)
#define XCOL_STRIDE 32
#define XROW_STRIDE (130 * XCOL_STRIDE)     // 4160
#define SX_OFF    SWF_BYTES                 // 9216
#define SX_BYTES  (6 * XROW_STRIDE)         // 24960
#define SBIAS_OFF (SX_OFF + SX_BYTES)       // 34176
#define SMEM_TOTAL (SBIAS_OFF + 128)        // 34304  (x4 = 137KB <= 228KB)

__device__ __forceinline__ void mma16816(float& c0, float& c1, float& c2, float& c3,
                                         uint32_t a0, uint32_t a1, uint32_t a2, uint32_t a3,
                                         uint32_t b0, uint32_t b1) {
    asm volatile("mma.sync.aligned.m16n8k16.row.col.f32.f16.f16.f32 "
                 "{%0,%1,%2,%3}, {%4,%5,%6,%7}, {%8,%9}, {%0,%1,%2,%3};"
                 : "+f"(c0), "+f"(c1), "+f"(c2), "+f"(c3)
                 : "r"(a0), "r"(a1), "r"(a2), "r"(a3), "r"(b0), "r"(b1));
}

__device__ __forceinline__ uint32_t h2pack(float v0, float v1) {
    __half2 h = __floats2half2_rn(v0, v1);
    return *(uint32_t*)&h;
}

// x-plane swizzle: fold addr bit7 into bit4 (keeps 8B alignment for LDS.64)
__device__ __forceinline__ uint32_t xswz(uint32_t a) {
    return a ^ (((a >> 7) & 1u) << 4);
}

__global__ __launch_bounds__(THREADS, 4)
void grouped_conv_hmma(const float* __restrict__ x,
                       const float* __restrict__ w,
                       const float* __restrict__ bias,
                       float* __restrict__ out)
{
    extern __shared__ char smem[];
    uint32_t* swf = (uint32_t*)(smem + SWF_OFF);
    char* sx = smem + SX_OFF;
    float* sbias = (float*)(smem + SBIAS_OFF);

    const int tid = threadIdx.x;
    const int wid = tid >> 5;
    const int lane = tid & 31;

    const int hb = blockIdx.x;          // 0..31  (4-row blocks)
    const int ng = blockIdx.y;          // 0..255
    const int n  = ng >> 4;
    const int g  = ng & 15;
    const int h0 = hb * 4;

    // ---- stage x: rows h0-1..h0+4, cols c 0..129 (gw = c-1), fp16 pairs ----
    // logical ci pair j stored at phys slot (j&3)*2 + (j>>2) -> LDS.64 frags
    const float* xg = x + (size_t)(n * 256 + g * 16) * 16384;
    for (int idx = tid; idx < 6 * 8 * 130; idx += THREADS) {
        int c   = idx % 130;
        int t   = idx / 130;
        int j   = t % 8;
        int r   = t / 8;                // 0..5
        int gh = h0 - 1 + r;
        int gw = c - 1;
        float v0 = 0.0f, v1 = 0.0f;
        if ((unsigned)gh < 128u && (unsigned)gw < 128u) {
            const float* p = xg + (j * 2) * 16384 + gh * 128 + gw;
            v0 = p[0];
            v1 = p[16384];
        }
        int phys = (j & 3) * 2 + (j >> 2);
        uint32_t off = (uint32_t)(r * XROW_STRIDE + c * XCOL_STRIDE + phys * 4);
        *(uint32_t*)(sx + xswz(off)) = h2pack(v0, v1);
    }

    // ---- stage W as B fragments (fp16), XOR-swizzled 32B/lane ----
    const float* wgp = w + (size_t)(g * 32) * 144;
    for (int idx = tid; idx < 9 * 32 * 8; idx += THREADS) {
        int slot  = idx & 7;
        int lane2 = (idx >> 3) & 31;
        int tap   = idx >> 8;           // 0..8
        int g4 = lane2 >> 2, t4 = lane2 & 3;
        int nt = slot >> 1, rr = slot & 1;
        int co  = nt * 8 + g4;
        int ci0 = 2 * t4 + 8 * rr;
        float v0 = wgp[co * 144 + ci0 * 9 + tap];
        float v1 = wgp[co * 144 + (ci0 + 1) * 9 + tap];
        uint32_t logical = (uint32_t)(tap * 1024 + lane2 * 32 + slot * 4);
        *(uint32_t*)((char*)swf + xswz(logical)) = h2pack(v0, v1);
    }
    if (tid < 32) sbias[tid] = bias[g * 32 + tid];
    __syncthreads();

    // ---- main: warp = (row, w-half); 2 halves of 2 segs each ----
    const int wrow  = wid >> 1;          // 0..3
    const int whalf = (wid & 1) * 64;
    const int g4 = lane >> 2, t4 = lane & 3;
    const int h = h0 + wrow;
    float* og = out + (size_t)(n * 512 + g * 32) * 16384 + (size_t)h * 128;

    // per-thread invariant A offset: pixel g4, frag pair t4 (a0 @ 8t4, a2 @ 8t4+4)
    const uint32_t pxoff = (uint32_t)(g4 * XCOL_STRIDE + t4 * 8);
    const uint32_t bswF = xswz((uint32_t)(lane * 32));

    #pragma unroll
    for (int half = 0; half < 2; ++half) {
        float acc[2][4][4];              // [seg2][nt][4]
        #pragma unroll
        for (int s = 0; s < 2; ++s)
            #pragma unroll
            for (int nt = 0; nt < 4; ++nt)
                #pragma unroll
                for (int i = 0; i < 4; ++i) acc[s][nt][i] = 0.0f;

        #pragma unroll 3
        for (int tap = 0; tap < 9; ++tap) {
            const int dh = tap / 3, dw = tap % 3;
            // B fragments for this tap
            const uint32_t bo = (uint32_t)(tap * 1024) + bswF;
            uint4 b0 = *(const uint4*)((const char*)swf + bo);
            uint4 b1 = *(const uint4*)((const char*)swf + (bo ^ 16));

            const uint32_t rowB = (uint32_t)((wrow + dh) * XROW_STRIDE
                                           + dw * XCOL_STRIDE) + pxoff;

            #pragma unroll
            for (int s = 0; s < 2; ++s) {
                const int w0 = whalf + (half * 2 + s) * 16;
                const uint32_t off = rowB + (uint32_t)(w0 * XCOL_STRIDE);
                // a0,a2 for px g4 (LDS.64); a1,a3 for px g4+8 (+256 keeps swizzle)
                uint2 v = *(const uint2*)(sx + xswz(off));
                uint2 u = *(const uint2*)(sx + xswz(off) + 256);

                float* a0 = acc[s][0];
                float* a1 = acc[s][1];
                float* a2 = acc[s][2];
                float* a3 = acc[s][3];

                mma16816(a0[0], a0[1], a0[2], a0[3], v.x, u.x, v.y, u.y, b0.x, b0.y);
                mma16816(a1[0], a1[1], a1[2], a1[3], v.x, u.x, v.y, u.y, b0.z, b0.w);
                mma16816(a2[0], a2[1], a2[2], a2[3], v.x, u.x, v.y, u.y, b1.x, b1.y);
                mma16816(a3[0], a3[1], a3[2], a3[3], v.x, u.x, v.y, u.y, b1.z, b1.w);
            }
        }

        // ---- epilogue for this half ----
        #pragma unroll
        for (int s = 0; s < 2; ++s) {
            const int w0 = whalf + (half * 2 + s) * 16;
            #pragma unroll
            for (int nt = 0; nt < 4; ++nt) {
                const float blo = sbias[nt * 8 + 2 * t4];
                const float bhi = sbias[nt * 8 + 2 * t4 + 1];
                const size_t co0 = (size_t)(nt * 8 + 2 * t4) * 16384;
                og[co0 + w0 + g4]             = acc[s][nt][0] + blo;
                og[co0 + 16384 + w0 + g4]     = acc[s][nt][1] + bhi;
                og[co0 + w0 + g4 + 8]         = acc[s][nt][2] + blo;
                og[co0 + 16384 + w0 + g4 + 8] = acc[s][nt][3] + bhi;
            }
        }
    }
}

extern "C" void kernel_launch(void* const* d_in, const int* in_sizes, int n_in,
                              void* d_out, int out_size)
{
    const float* x = (const float*)d_in[0];
    const float* w = (const float*)d_in[1];
    const float* b = (const float*)d_in[2];
    float* out = (float*)d_out;

    cudaFuncSetAttribute(grouped_conv_hmma,
                         cudaFuncAttributeMaxDynamicSharedMemorySize, SMEM_TOTAL);

    dim3 grid(32, 256);   // 4-row h blocks, n*16+g
    grouped_conv_hmma<<<grid, THREADS, SMEM_TOTAL>>>(x, w, b, out);
}

// round 12
// speedup vs baseline: 2.2900x; 1.1986x over previous
#include <cuda_runtime.h>
#include <cuda_fp16.h>
#include <cstdint>

// Grouped conv2d via implicit GEMM on mma.sync (HMMA), single-pass fp16.
// x[16,256,128,128] * W[512,16,3,3] (groups=16) + b -> out[16,512,128,128]
// R12 (= R11 + swizzle fix): operand swap (W = A m16k16, x = B n8k16):
//   - x B-frags: 2 conflict-free LDS.32 (slot t4 at ph, t4+4 at ph ^ 16)
//   - D frag holds adjacent pixels -> float2 epilogue stores
//   - staging: 1 STS.128 per thread-column, linear addresses (conflict-free)
//   - 8-row CTAs (512 threads), 2 CTAs/SM, 64 regs.

#define THREADS 512
#define ROWS 8

// ---- smem layout (bytes) ----
#define SWF_OFF   0
#define SWF_BYTES (9 * 1024)                // W frags: 9 taps x 32 lanes x 32B
#define XCOL_STRIDE 32
#define XROW_STRIDE (130 * XCOL_STRIDE)     // 4160
#define SX_OFF    SWF_BYTES                 // 9216
#define SX_BYTES  (10 * XROW_STRIDE)        // 41600 (ROWS+2 halo rows)
#define SBIAS_OFF (SX_OFF + SX_BYTES)       // 50816
#define SMEM_TOTAL (SBIAS_OFF + 128)        // 50944  (x2 CTA = 102KB <= 228KB)

__device__ __forceinline__ void mma16816(float& c0, float& c1, float& c2, float& c3,
                                         uint32_t a0, uint32_t a1, uint32_t a2, uint32_t a3,
                                         uint32_t b0, uint32_t b1) {
    asm volatile("mma.sync.aligned.m16n8k16.row.col.f32.f16.f16.f32 "
                 "{%0,%1,%2,%3}, {%4,%5,%6,%7}, {%8,%9}, {%0,%1,%2,%3};"
                 : "+f"(c0), "+f"(c1), "+f"(c2), "+f"(c3)
                 : "r"(a0), "r"(a1), "r"(a2), "r"(a3), "r"(b0), "r"(b1));
}

__device__ __forceinline__ uint32_t h2pack(float v0, float v1) {
    __half2 h = __floats2half2_rn(v0, v1);
    return *(uint32_t*)&h;
}

// fold addr bit7 into bit4 (16B-block xor; preserves 16B alignment)
__device__ __forceinline__ uint32_t xswz(uint32_t a) {
    return a ^ (((a >> 7) & 1u) << 4);
}

__global__ __launch_bounds__(THREADS, 2)
void grouped_conv_hmma(const float* __restrict__ x,
                       const float* __restrict__ w,
                       const float* __restrict__ bias,
                       float* __restrict__ out)
{
    extern __shared__ char smem[];
    char* swf = smem + SWF_OFF;
    char* sx  = smem + SX_OFF;
    float* sbias = (float*)(smem + SBIAS_OFF);

    const int tid = threadIdx.x;
    const int wid = tid >> 5;
    const int lane = tid & 31;

    const int hb = blockIdx.x;          // 0..15  (8-row blocks)
    const int ng = blockIdx.y;          // 0..255
    const int n  = ng >> 4;
    const int g  = ng & 15;
    const int h0 = hb * ROWS;

    // ---- stage x: rows h0-1..h0+8 (r 0..9), cols c 0..129 (gw = c-1) ----
    // thread packs 8 ci (= 4 pair-slots) of one column -> one STS.128.
    const float* xg = x + (size_t)(n * 256 + g * 16) * 16384;
    for (int idx = tid; idx < 10 * 2 * 130; idx += THREADS) {
        int c  = idx % 130;
        int t  = idx / 130;
        int hf = t & 1;                 // ci half: pairs 4hf..4hf+3
        int r  = t >> 1;                // 0..9
        int gh = h0 - 1 + r;
        int gw = c - 1;
        uint4 u = make_uint4(0u, 0u, 0u, 0u);
        if ((unsigned)gh < 128u && (unsigned)gw < 128u) {
            const float* p = xg + (size_t)(hf * 8) * 16384 + gh * 128 + gw;
            float v0 = p[0];
            float v1 = p[16384];
            float v2 = p[2 * 16384];
            float v3 = p[3 * 16384];
            float v4 = p[4 * 16384];
            float v5 = p[5 * 16384];
            float v6 = p[6 * 16384];
            float v7 = p[7 * 16384];
            u.x = h2pack(v0, v1);
            u.y = h2pack(v2, v3);
            u.z = h2pack(v4, v5);
            u.w = h2pack(v6, v7);
        }
        uint32_t lg = (uint32_t)(r * XROW_STRIDE + c * XCOL_STRIDE + hf * 16);
        *(uint4*)(sx + xswz(lg)) = u;
    }

    // ---- stage W as A fragments (m16k16): slot = mt*4 + frag-index ----
    const float* wgp = w + (size_t)(g * 32) * 144;
    for (int idx = tid; idx < 9 * 32 * 8; idx += THREADS) {
        int slot  = idx & 7;
        int lane2 = (idx >> 3) & 31;
        int tap   = idx >> 8;           // 0..8
        int mt = slot >> 2, fi = slot & 3;
        int co  = mt * 16 + (lane2 >> 2) + (fi & 1) * 8;
        int ci0 = 2 * (lane2 & 3) + (fi >> 1) * 8;
        float v0 = wgp[co * 144 + ci0 * 9 + tap];
        float v1 = wgp[co * 144 + (ci0 + 1) * 9 + tap];
        uint32_t lg = (uint32_t)(tap * 1024 + lane2 * 32 + slot * 4);
        *(uint32_t*)(swf + xswz(lg)) = h2pack(v0, v1);
    }
    if (tid < 32) sbias[tid] = bias[g * 32 + tid];
    __syncthreads();

    // ---- main: warp = (h-row wrow, px half whalf); 2 halves of 32px (4 n-tiles) ----
    const int wrow  = wid >> 1;          // 0..7
    const int whalf = (wid & 1) * 64;
    const int l4 = lane >> 2;            // B n-index / D m-row
    const int t4 = lane & 3;             // B k-pair / D px-pair
    float* og = out + (size_t)(n * 512 + g * 32) * 16384 + (size_t)(h0 + wrow) * 128;

    const float b00 = sbias[l4];         // mt0, rows l4 / l4+8
    const float b01 = sbias[l4 + 8];
    const float b10 = sbias[16 + l4];    // mt1
    const float b11 = sbias[16 + l4 + 8];

    const uint32_t bswF = xswz((uint32_t)(lane * 32));
    const uint32_t xbase = (uint32_t)(wrow * XROW_STRIDE + l4 * XCOL_STRIDE + t4 * 4);

    #pragma unroll
    for (int half = 0; half < 2; ++half) {
        float acc[4][2][4];              // [nt][mt][4]
        #pragma unroll
        for (int i = 0; i < 4; ++i)
            #pragma unroll
            for (int m = 0; m < 2; ++m)
                #pragma unroll
                for (int k = 0; k < 4; ++k) acc[i][m][k] = 0.0f;

        #pragma unroll 3
        for (int tap = 0; tap < 9; ++tap) {
            const int dh = tap / 3, dw = tap % 3;
            // A (weights) fragments, both m-tiles
            const uint32_t bo = (uint32_t)(tap * 1024) + bswF;
            uint4 awA = *(const uint4*)(swf + bo);          // mt0: a0..a3
            uint4 awB = *(const uint4*)(swf + (bo ^ 16));   // mt1

            const uint32_t rbase = xbase
                + (uint32_t)(dh * XROW_STRIDE + (whalf + half * 32 + dw) * XCOL_STRIDE);

            #pragma unroll
            for (int nt = 0; nt < 4; ++nt) {
                const uint32_t ph = xswz(rbase + (uint32_t)(nt * 8 * XCOL_STRIDE));
                uint32_t bx0 = *(const uint32_t*)(sx + ph);         // ci pair t4
                uint32_t bx1 = *(const uint32_t*)(sx + (ph ^ 16));  // ci pair t4+4 (swizzle-consistent)

                mma16816(acc[nt][0][0], acc[nt][0][1], acc[nt][0][2], acc[nt][0][3],
                         awA.x, awA.y, awA.z, awA.w, bx0, bx1);
                mma16816(acc[nt][1][0], acc[nt][1][1], acc[nt][1][2], acc[nt][1][3],
                         awB.x, awB.y, awB.z, awB.w, bx0, bx1);
            }
        }

        // ---- epilogue: adjacent-px float2 stores ----
        #pragma unroll
        for (int nt = 0; nt < 4; ++nt) {
            const int px = whalf + half * 32 + nt * 8 + 2 * t4;
            #pragma unroll
            for (int mt = 0; mt < 2; ++mt) {
                const float blo = mt ? b10 : b00;
                const float bhi = mt ? b11 : b01;
                float2 v01, v23;
                v01.x = acc[nt][mt][0] + blo;
                v01.y = acc[nt][mt][1] + blo;
                v23.x = acc[nt][mt][2] + bhi;
                v23.y = acc[nt][mt][3] + bhi;
                *(float2*)(og + (size_t)(mt * 16 + l4) * 16384 + px)       = v01;
                *(float2*)(og + (size_t)(mt * 16 + l4 + 8) * 16384 + px)   = v23;
            }
        }
    }
}

extern "C" void kernel_launch(void* const* d_in, const int* in_sizes, int n_in,
                              void* d_out, int out_size)
{
    const float* x = (const float*)d_in[0];
    const float* w = (const float*)d_in[1];
    const float* b = (const float*)d_in[2];
    float* out = (float*)d_out;

    cudaFuncSetAttribute(grouped_conv_hmma,
                         cudaFuncAttributeMaxDynamicSharedMemorySize, SMEM_TOTAL);

    dim3 grid(128 / ROWS, 256);   // 8-row h blocks, n*16+g
    grouped_conv_hmma<<<grid, THREADS, SMEM_TOTAL>>>(x, w, b, out);
}